// round 10
// baseline (speedup 1.0000x reference)
#include <cuda_runtime.h>
#include <cuda_bf16.h>
#include <cstdint>

typedef unsigned long long u64;
typedef unsigned int u32;

#define NB 16
#define NT 96
#define NN 325
#define ND 64
#define NH 64
#define NROWS (NB*NN)          // 5200
#define BTN (NB*NT*NN)         // 499200
#define HSTRIDE (NN*NH)        // 20800
#define BSTRIDE (NT*NN*NH)     // 1996800

// Fused scratch: [t][row][384] with row = b*NN+n; cols: f,i,o,u,gf,gu (64 each)
__device__ float g_AG[(size_t)BTN * 384];

// ================= helpers =================
__device__ __forceinline__ u32 smem_u32(const void* p){
    u32 a; asm("{ .reg .u64 t; cvta.to.shared.u64 t, %1; cvt.u32.u64 %0, t; }" : "=r"(a) : "l"(p));
    return a;
}
__device__ __forceinline__ u32 bfpack(float lo_elem, float hi_elem){
    u32 r; asm("cvt.rn.bf16x2.f32 %0, %1, %2;" : "=r"(r) : "f"(hi_elem), "f"(lo_elem));
    return r;
}
__device__ __forceinline__ void ldsm_x4(u32& a0,u32& a1,u32& a2,u32& a3, u32 addr){
    asm volatile("ldmatrix.sync.aligned.m8n8.x4.shared.b16 {%0,%1,%2,%3}, [%4];"
      : "=r"(a0),"=r"(a1),"=r"(a2),"=r"(a3) : "r"(addr));
}
__device__ __forceinline__ void ldsm_x2(u32& b0,u32& b1, u32 addr){
    asm volatile("ldmatrix.sync.aligned.m8n8.x2.shared.b16 {%0,%1}, [%2];"
      : "=r"(b0),"=r"(b1) : "r"(addr));
}
__device__ __forceinline__ void mma16816(float* c, const u32* a, const u32* b){
    asm volatile("mma.sync.aligned.m16n8k16.row.col.f32.bf16.bf16.f32 "
      "{%0,%1,%2,%3}, {%4,%5,%6,%7}, {%8,%9}, {%0,%1,%2,%3};"
      : "+f"(c[0]),"+f"(c[1]),"+f"(c[2]),"+f"(c[3])
      : "r"(a[0]),"r"(a[1]),"r"(a[2]),"r"(a[3]), "r"(b[0]),"r"(b[1]));
}

// =====================================================================
// Phase 1 (HMMA, proven R7-R9): per 64-row tile fused [xUx+bx | oUg+bg]
// (N=384), split-3 bf16, register prefetch pipelining.
// =====================================================================
#define P1_THREADS 256
#define P1_ROWS 64
#define P1_TILES (BTN/P1_ROWS)   // 7800
#define P1_GRID 148

#define PITCH 400
#define S_BIAS 0
#define S_B    1536
#define S_AX   155136
#define S_AO   180736
#define P1_SMEM 206336

__global__ void __launch_bounds__(P1_THREADS, 1)
glstm_pre_mma(const float* __restrict__ x, const float* __restrict__ osrc,
              const float* __restrict__ Ux, const float* __restrict__ bx,
              const float* __restrict__ Ug, const float* __restrict__ bg)
{
    extern __shared__ unsigned char smem[];
    float* bias_s = (float*)(smem + S_BIAS);
    const int tid = threadIdx.x;
    const int w   = tid >> 5;
    const int lane = tid & 31;
    const int gid = lane >> 2, tid4 = lane & 3;

    bias_s[tid] = bx[tid];
    if (tid < 128) bias_s[256 + tid] = bg[tid];

    for (int i = tid; i < 64*256; i += P1_THREADS){
        int n = i & 255, k = i >> 8;
        float v = Ux[k*256 + n];
        __nv_bfloat16 hb = __float2bfloat16(v);
        float lo = v - __bfloat162float(hb);
        __nv_bfloat16* row = (__nv_bfloat16*)(smem + S_B + n*PITCH);
        row[k] = hb; row[128 + k] = hb;
        row[64 + k] = __float2bfloat16(lo);
    }
    for (int i = tid; i < 64*128; i += P1_THREADS){
        int n = i & 127, k = i >> 7;
        float v = Ug[k*128 + n];
        __nv_bfloat16 hb = __float2bfloat16(v);
        float lo = v - __bfloat162float(hb);
        __nv_bfloat16* row = (__nv_bfloat16*)(smem + S_B + (256 + n)*PITCH);
        row[k] = hb; row[128 + k] = hb;
        row[64 + k] = __float2bfloat16(lo);
    }

    const u32 sb = smem_u32(smem);
    u32 rowAx[4], rowAo[4];
    #pragma unroll
    for (int mi = 0; mi < 4; mi++){
        u32 off = (u32)(16*mi + (lane & 15))*PITCH + ((lane >> 4) << 4);
        rowAx[mi] = sb + S_AX + off;
        rowAo[mi] = sb + S_AO + off;
    }
    u32 rowB[6];
    #pragma unroll
    for (int ni = 0; ni < 6; ni++)
        rowB[ni] = sb + S_B + (u32)(48*w + 8*ni + (lane & 7))*PITCH + (((lane >> 3) & 1) << 4);

    const bool needx = (w <= 5), needo = (w >= 5);

    const int cr = tid >> 2, ck0 = (tid & 3) << 4;
    u32* ax32 = (u32*)(smem + S_AX + cr*PITCH);
    u32* ao32 = (u32*)(smem + S_AO + cr*PITCH);

    int tile = blockIdx.x;
    float4 xv[4], ov[4];
    {
        const float4* xp = (const float4*)(x    + (size_t)((long long)tile*P1_ROWS + cr)*64 + ck0);
        const float4* op = (const float4*)(osrc + (size_t)((long long)tile*P1_ROWS + cr)*64 + ck0);
        #pragma unroll
        for (int j = 0; j < 4; j++){ xv[j] = xp[j]; ov[j] = op[j]; }
    }

    while (tile < P1_TILES){
        const long long m0 = (long long)tile * P1_ROWS;

        #pragma unroll
        for (int j = 0; j < 4; j++){
            #pragma unroll
            for (int h = 0; h < 2; h++){
                float a = h ? xv[j].z : xv[j].x;
                float b = h ? xv[j].w : xv[j].y;
                int k = ck0 + 4*j + 2*h;
                u32 hp = bfpack(a, b);
                float ra = a - __uint_as_float(hp << 16);
                float rb = b - __uint_as_float(hp & 0xFFFF0000u);
                u32 lp = bfpack(ra, rb);
                ax32[k>>1] = hp; ax32[32 + (k>>1)] = hp; ax32[64 + (k>>1)] = lp;

                a = h ? ov[j].z : ov[j].x;
                b = h ? ov[j].w : ov[j].y;
                hp = bfpack(a, b);
                ra = a - __uint_as_float(hp << 16);
                rb = b - __uint_as_float(hp & 0xFFFF0000u);
                lp = bfpack(ra, rb);
                ao32[k>>1] = hp; ao32[32 + (k>>1)] = hp; ao32[64 + (k>>1)] = lp;
            }
        }
        __syncthreads();

        const int nxt = tile + gridDim.x;
        if (nxt < P1_TILES){
            const float4* xp = (const float4*)(x    + (size_t)((long long)nxt*P1_ROWS + cr)*64 + ck0);
            const float4* op = (const float4*)(osrc + (size_t)((long long)nxt*P1_ROWS + cr)*64 + ck0);
            #pragma unroll
            for (int j = 0; j < 4; j++){ xv[j] = xp[j]; ov[j] = op[j]; }
        }

        float acc[4][6][4];
        #pragma unroll
        for (int mi = 0; mi < 4; mi++)
            #pragma unroll
            for (int ni = 0; ni < 6; ni++)
                #pragma unroll
                for (int e = 0; e < 4; e++) acc[mi][ni][e] = 0.0f;

        #pragma unroll
        for (int kf = 0; kf < 12; kf++){
            u32 Axf[4][4], Aof[4][4];
            if (needx){
                #pragma unroll
                for (int mi = 0; mi < 4; mi++)
                    ldsm_x4(Axf[mi][0],Axf[mi][1],Axf[mi][2],Axf[mi][3], rowAx[mi] + kf*32);
            }
            if (needo){
                #pragma unroll
                for (int mi = 0; mi < 4; mi++)
                    ldsm_x4(Aof[mi][0],Aof[mi][1],Aof[mi][2],Aof[mi][3], rowAo[mi] + kf*32);
            }
            u32 Bf[6][2];
            #pragma unroll
            for (int ni = 0; ni < 6; ni++)
                ldsm_x2(Bf[ni][0], Bf[ni][1], rowB[ni] + kf*32);

            #pragma unroll
            for (int ni = 0; ni < 6; ni++){
                const bool isx = (48*w + 8*ni) < 256;
                #pragma unroll
                for (int mi = 0; mi < 4; mi++)
                    mma16816(acc[mi][ni], isx ? Axf[mi] : Aof[mi], Bf[ni]);
            }
        }
        __syncthreads();

        #pragma unroll
        for (int mi = 0; mi < 4; mi++){
            #pragma unroll
            for (int half = 0; half < 2; half++){
                int r = 16*mi + gid + 8*half;
                long long m = m0 + r;
                u32 mu = (u32)m;
                u32 qq = mu / NN;
                u32 n  = mu - qq*NN;
                u32 t  = qq % NT, b = qq / NT;
                size_t ro = (size_t)t*NROWS + (size_t)b*NN + n;
                float* pAG = g_AG + ro*384;
                #pragma unroll
                for (int ni = 0; ni < 6; ni++){
                    int col = 48*w + 8*ni + 2*tid4;
                    float2 bv = *(const float2*)&bias_s[col];
                    float2 cv;
                    cv.x = acc[mi][ni][half*2 + 0] + bv.x;
                    cv.y = acc[mi][ni][half*2 + 1] + bv.y;
                    *(float2*)(pAG + col) = cv;
                }
            }
        }
        tile = nxt;
    }
}

// =====================================================================
// Phase 2: HMMA recurrence, persistent-B-in-registers, half-pipelined.
// 130 blocks x 40 rows; halves A (24 rows, pad 32) / B (16 rows).
// 16 warps x 24 N-cols; every warp: cp.async(own gates chunks) -> EW
// (other half, prev t) -> MMA(this half) -> RMW. 1 barrier per slot.
// =====================================================================
#define P2_THREADS 512
#define P2_R 40
#define P2_BLOCKS 130
#define HPITCH 272                   // bytes per h row (hi 128 | lo 128 + pad)
#define GP 388                       // gates pitch (f32 words)
#define SB_H   0                     // hA 32*272=8704, hB 16*272=4352 -> 13056
#define SB_HB  8704
#define SB_STG 13056                 // weight staging 384*272 = 104448 (init only)
#define SB_GA  13056                 // 24*GP*4 = 37248 (overlays staging)
#define SB_GB  (13056 + 24*GP*4)     // 50304; 16*GP*4 = 24832
#define P2_SMEM (SB_STG + 104448)    // 117504

__device__ __forceinline__ void lstm_elem(const float* g, float& c0, float& c1,
                                          float& hn0, float& hn1){
    float2 gf_ = *(const float2*)(g + 0);
    float2 gi_ = *(const float2*)(g + 64);
    float2 go_ = *(const float2*)(g + 128);
    float2 gu_ = *(const float2*)(g + 192);
    float2 gG_ = *(const float2*)(g + 256);
    float2 gV_ = *(const float2*)(g + 320);
    {
        float ef = __expf(-gf_.x);
        float eg = __expf(-gG_.x);
        float fgf = __fdividef(1.0f, 1.0f + ef + eg + ef*eg);
        float ei = __expf(-gi_.x);
        float eu = __expf(-gu_.x);
        float ev = __expf(-gV_.x);
        float iuu = __fdividef(1.0f, (1.0f+ei)*(1.0f+eu)*(1.0f+ev));
        float c = fgf*c0 + iuu;
        c0 = c;
        float ot = __fdividef(1.0f, 1.0f + __expf(-go_.x));
        float th = 1.0f - __fdividef(2.0f, 1.0f + __expf(2.0f*c));
        hn0 = ot * th;
    }
    {
        float ef = __expf(-gf_.y);
        float eg = __expf(-gG_.y);
        float fgf = __fdividef(1.0f, 1.0f + ef + eg + ef*eg);
        float ei = __expf(-gi_.y);
        float eu = __expf(-gu_.y);
        float ev = __expf(-gV_.y);
        float iuu = __fdividef(1.0f, (1.0f+ei)*(1.0f+eu)*(1.0f+ev));
        float c = fgf*c1 + iuu;
        c1 = c;
        float ot = __fdividef(1.0f, 1.0f + __expf(-go_.y));
        float th = 1.0f - __fdividef(2.0f, 1.0f + __expf(2.0f*c));
        hn1 = ot * th;
    }
}

// write h element pair (fp32) as hi/lo bf16 into h buffer
__device__ __forceinline__ void store_h(unsigned char* smem, u32 hoff, int r, int hp,
                                        float hn0, float hn1){
    u32 hhi = bfpack(hn0, hn1);
    float r0 = hn0 - __uint_as_float(hhi << 16);
    float r1 = hn1 - __uint_as_float(hhi & 0xFFFF0000u);
    u32 hlo = bfpack(r0, r1);
    *(u32*)(smem + hoff + r*HPITCH + 4*hp)       = hhi;
    *(u32*)(smem + hoff + r*HPITCH + 128 + 4*hp) = hlo;
}

// MMA for one half: MI m16-tiles, NRG valid row-groups (rg -> mi=rg>>1, hm=rg&1)
template<int MI, int NRG>
__device__ __forceinline__ void mma_half(
    unsigned char* smem, u32 sb, u32 hoff, u32 goff,
    const float* apre_src, int lane, int w, int gid, int tid4,
    const u32 Bh[3][4][2], const u32 Bl[3][4][2])
{
    u32 rowA[MI];
    #pragma unroll
    for (int mi = 0; mi < MI; mi++)
        rowA[mi] = sb + hoff + (u32)(16*mi + (lane & 15))*HPITCH + ((lane >> 4) << 4);

    float acc[MI][3][4];
    #pragma unroll
    for (int mi = 0; mi < MI; mi++)
        #pragma unroll
        for (int ni = 0; ni < 3; ni++)
            #pragma unroll
            for (int e = 0; e < 4; e++) acc[mi][ni][e] = 0.0f;

    #pragma unroll
    for (int kf = 0; kf < 4; kf++){
        u32 Ah[MI][4], Al[MI][4];
        #pragma unroll
        for (int mi = 0; mi < MI; mi++){
            ldsm_x4(Ah[mi][0],Ah[mi][1],Ah[mi][2],Ah[mi][3], rowA[mi] + kf*32);
            ldsm_x4(Al[mi][0],Al[mi][1],Al[mi][2],Al[mi][3], rowA[mi] + 128 + kf*32);
        }
        #pragma unroll
        for (int ni = 0; ni < 3; ni++)
            #pragma unroll
            for (int mi = 0; mi < MI; mi++){
                mma16816(acc[mi][ni], Ah[mi], Bh[ni][kf]);
                mma16816(acc[mi][ni], Ah[mi], Bl[ni][kf]);
                mma16816(acc[mi][ni], Al[mi], Bh[ni][kf]);
            }
    }

    // own apre chunks landed (issued before call); RMW only own positions
    asm volatile("cp.async.wait_group 0;" ::: "memory");
    float* gates = (float*)(smem + goff);
    #pragma unroll
    for (int rg = 0; rg < NRG; rg++){
        int mi = rg >> 1, hm = rg & 1;
        int r = 16*mi + gid + 8*hm;
        #pragma unroll
        for (int ni = 0; ni < 3; ni++){
            int col = 24*w + 8*ni + 2*tid4;
            float* gp = gates + (size_t)r*GP + col;
            float2 prev = *(const float2*)gp;
            *(float2*)gp = make_float2(acc[mi][ni][2*hm]   + prev.x,
                                       acc[mi][ni][2*hm+1] + prev.y);
        }
    }
}

__global__ void __launch_bounds__(P2_THREADS, 1)
glstm_rec_mma(const float* __restrict__ Vx, const float* __restrict__ Vg,
              float* __restrict__ hidden, float* __restrict__ htp, float* __restrict__ ctp)
{
    extern __shared__ unsigned char smem[];
    const u32 sb = smem_u32(smem);

    const int tid  = threadIdx.x;
    const int lane = tid & 31;
    const int w    = tid >> 5;      // 0..15
    const int gid  = lane >> 2, tid4 = lane & 3;
    const int blk  = blockIdx.x;

    // ---- stage fused weights [Vx|Vg] as [n][hi|lo] bf16, then load to regs ----
    for (int i = tid; i < 64*384; i += P2_THREADS){
        int k = i / 384, n = i - k*384;
        float v = (n < 256) ? Vx[k*256 + n] : Vg[k*128 + (n - 256)];
        __nv_bfloat16 hb = __float2bfloat16(v);
        __nv_bfloat16* row = (__nv_bfloat16*)(smem + SB_STG + n*HPITCH);
        row[k]      = hb;
        row[64 + k] = __float2bfloat16(v - __bfloat162float(hb));
    }
    __syncthreads();

    u32 Bh[3][4][2], Bl[3][4][2];
    {
        #pragma unroll
        for (int ni = 0; ni < 3; ni++){
            u32 rb = sb + SB_STG + (u32)(24*w + 8*ni + (lane & 7))*HPITCH
                   + (((lane >> 3) & 1) << 4);
            #pragma unroll
            for (int kf = 0; kf < 4; kf++){
                ldsm_x2(Bh[ni][kf][0], Bh[ni][kf][1], rb + kf*32);
                ldsm_x2(Bl[ni][kf][0], Bl[ni][kf][1], rb + 128 + kf*32);
            }
        }
    }
    __syncthreads();   // staging reads done; region becomes gates

    // ---- zero h buffers (13056 B) ----
    for (int i = tid; i < 13056/4; i += P2_THREADS)
        ((u32*)smem)[i] = 0;

    // ---- EW state ----
    // half A: 768 pairs -> thread handles pair tid (all) + 512+tid (tid<256)
    // half B: 512 pairs -> thread handles pair tid
    float cA0[2], cA1[2], cB0, cB1;
    int gA[2], fA[2], gB, fB;
    cA0[0]=cA0[1]=cA1[0]=cA1[1]=cB0=cB1 = 0.0f;
    {
        #pragma unroll
        for (int j = 0; j < 2; j++){
            int p = tid + j*P2_THREADS;
            int r = p >> 5, hp = p & 31;
            int rho = blk*P2_R + ((p < 768) ? r : 0);
            int b = rho / NN, n = rho - b*NN;
            gA[j] = b*BSTRIDE + n*NH + 2*hp;
            fA[j] = rho*NH + 2*hp;
        }
        int r = tid >> 5, hp = tid & 31;
        int rho = blk*P2_R + 24 + r;
        int b = rho / NN, n = rho - b*NN;
        gB = b*BSTRIDE + n*NH + 2*hp;
        fB = rho*NH + 2*hp;
    }
    const int nA = (tid < 256) ? 2 : 1;
    __syncthreads();

    for (int s = 0; s < 2*NT + 1; s++){
        const bool doM = (s < 2*NT);
        const int hs = s & 1;                 // MMA half
        const int tM = s >> 1;

        // ---- 1) cp.async own gate chunks for (hs, tM) ----
        if (doM){
            const float* apre = g_AG
                + ((size_t)tM*NROWS + (size_t)blk*P2_R + (hs ? 24 : 0))*384;
            const u32 goff = hs ? SB_GB : SB_GA;
            const int nrg = hs ? 2 : 3;
            #pragma unroll
            for (int rg = 0; rg < 3; rg++){
                if (rg < nrg){
                    int r = 8*rg + gid;
                    #pragma unroll
                    for (int ni = 0; ni < 3; ni++){
                        int col = 24*w + 8*ni + 2*tid4;
                        u32 dst = sb + goff + (u32)r*(GP*4) + (u32)col*4;
                        const float* src = apre + (size_t)r*384 + col;
                        asm volatile("cp.async.ca.shared.global [%0], [%1], 8;"
                                     :: "r"(dst), "l"(src) : "memory");
                    }
                }
            }
            asm volatile("cp.async.commit_group;" ::: "memory");
        }

        // ---- 2) EW for other half, step (s-1)>>1 ----
        if (s > 0){
            const int he = (s - 1) & 1, tE = (s - 1) >> 1;
            if (he == 0){
                float* gates = (float*)(smem + SB_GA);
                #pragma unroll
                for (int j = 0; j < 2; j++){
                    if (j < nA){
                        int p = tid + j*P2_THREADS;
                        int r = p >> 5, hp = p & 31;
                        float hn0, hn1;
                        lstm_elem(gates + (size_t)r*GP + 2*hp, cA0[j], cA1[j], hn0, hn1);
                        store_h(smem, SB_H, r, hp, hn0, hn1);
                        float2 hv = make_float2(hn0, hn1);
                        *(float2*)&hidden[gA[j] + tE*HSTRIDE] = hv;
                        if (tE == NT-1){
                            *(float2*)&htp[fA[j]] = hv;
                            *(float2*)&ctp[fA[j]] = make_float2(cA0[j], cA1[j]);
                        }
                    }
                }
            } else {
                float* gates = (float*)(smem + SB_GB);
                int r = tid >> 5, hp = tid & 31;
                float hn0, hn1;
                lstm_elem(gates + (size_t)r*GP + 2*hp, cB0, cB1, hn0, hn1);
                store_h(smem, SB_HB, r, hp, hn0, hn1);
                float2 hv = make_float2(hn0, hn1);
                *(float2*)&hidden[gB + tE*HSTRIDE] = hv;
                if (tE == NT-1){
                    *(float2*)&htp[fB] = hv;
                    *(float2*)&ctp[fB] = make_float2(cB0, cB1);
                }
            }
        }

        // ---- 3) MMA(hs, tM) + RMW gates ----
        if (doM){
            if (hs == 0)
                mma_half<2,3>(smem, sb, SB_H,  SB_GA,
                              nullptr, lane, w, gid, tid4, Bh, Bl);
            else
                mma_half<1,2>(smem, sb, SB_HB, SB_GB,
                              nullptr, lane, w, gid, tid4, Bh, Bl);
        } else {
            asm volatile("cp.async.wait_group 0;" ::: "memory");
        }

        __syncthreads();   // slot boundary: gates(s) + h(s-1) published
    }
}

extern "C" void kernel_launch(void* const* d_in, const int* in_sizes, int n_in,
                              void* d_out, int out_size)
{
    const float* x   = (const float*)d_in[0];
    const float* o_s = (const float*)d_in[1];
    const float* Ux  = (const float*)d_in[2];
    const float* Vx  = (const float*)d_in[3];
    const float* bx  = (const float*)d_in[4];
    const float* Ug  = (const float*)d_in[5];
    const float* Vg  = (const float*)d_in[6];
    const float* bg  = (const float*)d_in[7];

    float* out    = (float*)d_out;
    float* hidden = out;                               // [B,T,N,H]
    float* htp    = out + (size_t)BTN * NH;            // [B,N,H]
    float* ctp    = htp + (size_t)NROWS * NH;          // [B,N,H]

    cudaFuncSetAttribute(glstm_pre_mma, cudaFuncAttributeMaxDynamicSharedMemorySize, P1_SMEM);
    cudaFuncSetAttribute(glstm_rec_mma, cudaFuncAttributeMaxDynamicSharedMemorySize, P2_SMEM);

    glstm_pre_mma<<<P1_GRID, P1_THREADS, P1_SMEM>>>(x, o_s, Ux, bx, Ug, bg);
    glstm_rec_mma<<<P2_BLOCKS, P2_THREADS, P2_SMEM>>>(Vx, Vg, hidden, htp, ctp);
}

// round 11
// speedup vs baseline: 1.1062x; 1.1062x over previous
#include <cuda_runtime.h>
#include <cuda_bf16.h>
#include <cstdint>

typedef unsigned long long u64;
typedef unsigned int u32;

#define NB 16
#define NT 96
#define NN 325
#define ND 64
#define NH 64
#define NROWS (NB*NN)          // 5200
#define BTN (NB*NT*NN)         // 499200
#define HSTRIDE (NN*NH)        // 20800
#define BSTRIDE (NT*NN*NH)     // 1996800

// Fused scratch: [t][row][384] with row = b*NN+n; cols: f,i,o,u,gf,gu (64 each)
__device__ float g_AG[(size_t)BTN * 384];

// ================= helpers =================
__device__ __forceinline__ u32 smem_u32(const void* p){
    u32 a; asm("{ .reg .u64 t; cvta.to.shared.u64 t, %1; cvt.u32.u64 %0, t; }" : "=r"(a) : "l"(p));
    return a;
}
__device__ __forceinline__ u32 bfpack(float lo_elem, float hi_elem){
    u32 r; asm("cvt.rn.bf16x2.f32 %0, %1, %2;" : "=r"(r) : "f"(hi_elem), "f"(lo_elem));
    return r;
}
__device__ __forceinline__ void ldsm_x4(u32& a0,u32& a1,u32& a2,u32& a3, u32 addr){
    asm volatile("ldmatrix.sync.aligned.m8n8.x4.shared.b16 {%0,%1,%2,%3}, [%4];"
      : "=r"(a0),"=r"(a1),"=r"(a2),"=r"(a3) : "r"(addr));
}
__device__ __forceinline__ void ldsm_x2(u32& b0,u32& b1, u32 addr){
    asm volatile("ldmatrix.sync.aligned.m8n8.x2.shared.b16 {%0,%1}, [%2];"
      : "=r"(b0),"=r"(b1) : "r"(addr));
}
__device__ __forceinline__ void mma16816(float* c, const u32* a, const u32* b){
    asm volatile("mma.sync.aligned.m16n8k16.row.col.f32.bf16.bf16.f32 "
      "{%0,%1,%2,%3}, {%4,%5,%6,%7}, {%8,%9}, {%0,%1,%2,%3};"
      : "+f"(c[0]),"+f"(c[1]),"+f"(c[2]),"+f"(c[3])
      : "r"(a[0]),"r"(a[1]),"r"(a[2]),"r"(a[3]), "r"(b[0]),"r"(b[1]));
}

// =====================================================================
// Phase 1 (HMMA, proven R7-R9): per 64-row tile fused [xUx+bx | oUg+bg]
// (N=384), split-3 bf16, register prefetch pipelining.
// =====================================================================
#define P1_THREADS 256
#define P1_ROWS 64
#define P1_TILES (BTN/P1_ROWS)   // 7800
#define P1_GRID 148

#define PITCH 400
#define S_BIAS 0
#define S_B    1536
#define S_AX   155136
#define S_AO   180736
#define P1_SMEM 206336

__global__ void __launch_bounds__(P1_THREADS, 1)
glstm_pre_mma(const float* __restrict__ x, const float* __restrict__ osrc,
              const float* __restrict__ Ux, const float* __restrict__ bx,
              const float* __restrict__ Ug, const float* __restrict__ bg)
{
    extern __shared__ unsigned char smem[];
    float* bias_s = (float*)(smem + S_BIAS);
    const int tid = threadIdx.x;
    const int w   = tid >> 5;
    const int lane = tid & 31;
    const int gid = lane >> 2, tid4 = lane & 3;

    bias_s[tid] = bx[tid];
    if (tid < 128) bias_s[256 + tid] = bg[tid];

    for (int i = tid; i < 64*256; i += P1_THREADS){
        int n = i & 255, k = i >> 8;
        float v = Ux[k*256 + n];
        __nv_bfloat16 hb = __float2bfloat16(v);
        float lo = v - __bfloat162float(hb);
        __nv_bfloat16* row = (__nv_bfloat16*)(smem + S_B + n*PITCH);
        row[k] = hb; row[128 + k] = hb;
        row[64 + k] = __float2bfloat16(lo);
    }
    for (int i = tid; i < 64*128; i += P1_THREADS){
        int n = i & 127, k = i >> 7;
        float v = Ug[k*128 + n];
        __nv_bfloat16 hb = __float2bfloat16(v);
        float lo = v - __bfloat162float(hb);
        __nv_bfloat16* row = (__nv_bfloat16*)(smem + S_B + (256 + n)*PITCH);
        row[k] = hb; row[128 + k] = hb;
        row[64 + k] = __float2bfloat16(lo);
    }

    const u32 sb = smem_u32(smem);
    u32 rowAx[4], rowAo[4];
    #pragma unroll
    for (int mi = 0; mi < 4; mi++){
        u32 off = (u32)(16*mi + (lane & 15))*PITCH + ((lane >> 4) << 4);
        rowAx[mi] = sb + S_AX + off;
        rowAo[mi] = sb + S_AO + off;
    }
    u32 rowB[6];
    #pragma unroll
    for (int ni = 0; ni < 6; ni++)
        rowB[ni] = sb + S_B + (u32)(48*w + 8*ni + (lane & 7))*PITCH + (((lane >> 3) & 1) << 4);

    const bool needx = (w <= 5), needo = (w >= 5);

    const int cr = tid >> 2, ck0 = (tid & 3) << 4;
    u32* ax32 = (u32*)(smem + S_AX + cr*PITCH);
    u32* ao32 = (u32*)(smem + S_AO + cr*PITCH);

    int tile = blockIdx.x;
    float4 xv[4], ov[4];
    {
        const float4* xp = (const float4*)(x    + (size_t)((long long)tile*P1_ROWS + cr)*64 + ck0);
        const float4* op = (const float4*)(osrc + (size_t)((long long)tile*P1_ROWS + cr)*64 + ck0);
        #pragma unroll
        for (int j = 0; j < 4; j++){ xv[j] = xp[j]; ov[j] = op[j]; }
    }

    while (tile < P1_TILES){
        const long long m0 = (long long)tile * P1_ROWS;

        #pragma unroll
        for (int j = 0; j < 4; j++){
            #pragma unroll
            for (int h = 0; h < 2; h++){
                float a = h ? xv[j].z : xv[j].x;
                float b = h ? xv[j].w : xv[j].y;
                int k = ck0 + 4*j + 2*h;
                u32 hp = bfpack(a, b);
                float ra = a - __uint_as_float(hp << 16);
                float rb = b - __uint_as_float(hp & 0xFFFF0000u);
                u32 lp = bfpack(ra, rb);
                ax32[k>>1] = hp; ax32[32 + (k>>1)] = hp; ax32[64 + (k>>1)] = lp;

                a = h ? ov[j].z : ov[j].x;
                b = h ? ov[j].w : ov[j].y;
                hp = bfpack(a, b);
                ra = a - __uint_as_float(hp << 16);
                rb = b - __uint_as_float(hp & 0xFFFF0000u);
                lp = bfpack(ra, rb);
                ao32[k>>1] = hp; ao32[32 + (k>>1)] = hp; ao32[64 + (k>>1)] = lp;
            }
        }
        __syncthreads();

        const int nxt = tile + gridDim.x;
        if (nxt < P1_TILES){
            const float4* xp = (const float4*)(x    + (size_t)((long long)nxt*P1_ROWS + cr)*64 + ck0);
            const float4* op = (const float4*)(osrc + (size_t)((long long)nxt*P1_ROWS + cr)*64 + ck0);
            #pragma unroll
            for (int j = 0; j < 4; j++){ xv[j] = xp[j]; ov[j] = op[j]; }
        }

        float acc[4][6][4];
        #pragma unroll
        for (int mi = 0; mi < 4; mi++)
            #pragma unroll
            for (int ni = 0; ni < 6; ni++)
                #pragma unroll
                for (int e = 0; e < 4; e++) acc[mi][ni][e] = 0.0f;

        #pragma unroll
        for (int kf = 0; kf < 12; kf++){
            u32 Axf[4][4], Aof[4][4];
            if (needx){
                #pragma unroll
                for (int mi = 0; mi < 4; mi++)
                    ldsm_x4(Axf[mi][0],Axf[mi][1],Axf[mi][2],Axf[mi][3], rowAx[mi] + kf*32);
            }
            if (needo){
                #pragma unroll
                for (int mi = 0; mi < 4; mi++)
                    ldsm_x4(Aof[mi][0],Aof[mi][1],Aof[mi][2],Aof[mi][3], rowAo[mi] + kf*32);
            }
            u32 Bf[6][2];
            #pragma unroll
            for (int ni = 0; ni < 6; ni++)
                ldsm_x2(Bf[ni][0], Bf[ni][1], rowB[ni] + kf*32);

            #pragma unroll
            for (int ni = 0; ni < 6; ni++){
                const bool isx = (48*w + 8*ni) < 256;
                #pragma unroll
                for (int mi = 0; mi < 4; mi++)
                    mma16816(acc[mi][ni], isx ? Axf[mi] : Aof[mi], Bf[ni]);
            }
        }
        __syncthreads();

        #pragma unroll
        for (int mi = 0; mi < 4; mi++){
            #pragma unroll
            for (int half = 0; half < 2; half++){
                int r = 16*mi + gid + 8*half;
                long long m = m0 + r;
                u32 mu = (u32)m;
                u32 qq = mu / NN;
                u32 n  = mu - qq*NN;
                u32 t  = qq % NT, b = qq / NT;
                size_t ro = (size_t)t*NROWS + (size_t)b*NN + n;
                float* pAG = g_AG + ro*384;
                #pragma unroll
                for (int ni = 0; ni < 6; ni++){
                    int col = 48*w + 8*ni + 2*tid4;
                    float2 bv = *(const float2*)&bias_s[col];
                    float2 cv;
                    cv.x = acc[mi][ni][half*2 + 0] + bv.x;
                    cv.y = acc[mi][ni][half*2 + 1] + bv.y;
                    *(float2*)(pAG + col) = cv;
                }
            }
        }
        tile = nxt;
    }
}

// =====================================================================
// Phase 2: HMMA recurrence with gate-aligned fragment ownership.
// 130 blocks x 40 rows (pad 48). 256 threads, 8 warps.
// Warp w's six 8-col MMA slices = one slice per GATE: cols 64g + 8w.
// -> thread's acc holds all 6 gates of its element pairs: EW is fully
// in-register; NO gates smem buffer. apre prefetched into regs (t+1).
// Ping-pong h buffers; ONE __syncthreads per step.
// =====================================================================
#define P2_THREADS 256
#define P2_R 40
#define P2_BLOCKS 130
#define HPITCH 272                   // bytes per h/B row (hi 128 | lo 128 + pad)
#define SB_B   0                     // 384*272 = 104448
#define SB_H0  104448                // 48*272 = 13056
#define SB_H1  (104448 + 13056)      // 13056
#define P2_SMEM (104448 + 2*13056)   // 130560

__global__ void __launch_bounds__(P2_THREADS, 1)
glstm_rec_mma(const float* __restrict__ Vx, const float* __restrict__ Vg,
              float* __restrict__ hidden, float* __restrict__ htp, float* __restrict__ ctp)
{
    extern __shared__ unsigned char smem[];
    const u32 sb = smem_u32(smem);

    const int tid  = threadIdx.x;
    const int lane = tid & 31;
    const int w    = tid >> 5;      // 0..7
    const int gid  = lane >> 2, tid4 = lane & 3;
    const int blk  = blockIdx.x;
    const int hcol = 8*w + 2*tid4;  // h column pair owned by this thread

    // ---- build fused B = [Vx | Vg] rows n=0..383 as [hi(64)|lo(64)] bf16 ----
    for (int i = tid; i < 64*384; i += P2_THREADS){
        int k = i / 384, n = i - k*384;
        float v = (n < 256) ? Vx[k*256 + n] : Vg[k*128 + (n - 256)];
        __nv_bfloat16 hb = __float2bfloat16(v);
        __nv_bfloat16* row = (__nv_bfloat16*)(smem + SB_B + n*HPITCH);
        row[k]      = hb;
        row[64 + k] = __float2bfloat16(v - __bfloat162float(hb));
    }
    // ---- zero both h buffers (incl. pad rows) ----
    for (int i = tid; i < 2*13056/4; i += P2_THREADS)
        ((u32*)(smem + SB_H0))[i] = 0;

    // B ldmatrix addresses: gate g -> rows 64g + 8w .. +7
    u32 rowB[6];
    #pragma unroll
    for (int g = 0; g < 6; g++)
        rowB[g] = sb + SB_B + (u32)(64*g + 8*w + (lane & 7))*HPITCH
                + (((lane >> 3) & 1) << 4);

    // row groups rg=0..4: (mi,hm) = (0,0),(0,1),(1,0),(1,1),(2,0); r=16mi+8hm+gid
    int rrow[5], rhoA[5], gb[5], fb[5];
    float cst0[5], cst1[5];
    #pragma unroll
    for (int rg = 0; rg < 5; rg++){
        int mi = rg >> 1, hm = rg & 1;
        int r = 16*mi + 8*hm + gid;
        rrow[rg] = r;
        int rho = blk*P2_R + r;          // < 5200
        rhoA[rg] = rho;
        int b = rho / NN, n = rho - b*NN;
        gb[rg] = b*BSTRIDE + n*NH + hcol;
        fb[rg] = rho*NH + hcol;
        cst0[rg] = 0.0f; cst1[rg] = 0.0f;
    }
    __syncthreads();

    // ---- prefetch apre for t=0 ----
    float2 ap[5][6];
    #pragma unroll
    for (int rg = 0; rg < 5; rg++){
        const float* p = g_AG + (size_t)rhoA[rg]*384 + hcol;
        #pragma unroll
        for (int g = 0; g < 6; g++) ap[rg][g] = *(const float2*)(p + 64*g);
    }

    for (int t = 0; t < NT; t++){
        const u32 hin  = (t & 1) ? SB_H1 : SB_H0;
        const u32 hout = (t & 1) ? SB_H0 : SB_H1;

        // ---- acc init = apre (gate-aligned fragments); pad rows -> 0 ----
        float acc[3][6][4];
        #pragma unroll
        for (int mi = 0; mi < 3; mi++){
            #pragma unroll
            for (int g = 0; g < 6; g++){
                int rg0 = 2*mi, rg1 = 2*mi + 1;
                acc[mi][g][0] = ap[rg0][g].x;
                acc[mi][g][1] = ap[rg0][g].y;
                if (mi < 2){
                    acc[mi][g][2] = ap[rg1][g].x;
                    acc[mi][g][3] = ap[rg1][g].y;
                } else {
                    acc[mi][g][2] = 0.0f; acc[mi][g][3] = 0.0f;
                }
            }
        }

        // ---- prefetch apre for t+1 (hidden under MMA) ----
        if (t + 1 < NT){
            #pragma unroll
            for (int rg = 0; rg < 5; rg++){
                const float* p = g_AG + ((size_t)(t+1)*NROWS + rhoA[rg])*384 + hcol;
                #pragma unroll
                for (int g = 0; g < 6; g++) ap[rg][g] = *(const float2*)(p + 64*g);
            }
        }

        // ---- MMA: fused split-3 per kf ----
        u32 rowA[3];
        #pragma unroll
        for (int mi = 0; mi < 3; mi++)
            rowA[mi] = sb + hin + (u32)(16*mi + (lane & 15))*HPITCH + ((lane >> 4) << 4);

        #pragma unroll
        for (int kf = 0; kf < 4; kf++){
            u32 Ah[3][4], Al[3][4];
            #pragma unroll
            for (int mi = 0; mi < 3; mi++){
                ldsm_x4(Ah[mi][0],Ah[mi][1],Ah[mi][2],Ah[mi][3], rowA[mi] + kf*32);
                ldsm_x4(Al[mi][0],Al[mi][1],Al[mi][2],Al[mi][3], rowA[mi] + 128 + kf*32);
            }
            u32 Bh[6][2], Bl[6][2];
            #pragma unroll
            for (int g = 0; g < 6; g++){
                ldsm_x2(Bh[g][0], Bh[g][1], rowB[g] + kf*32);
                ldsm_x2(Bl[g][0], Bl[g][1], rowB[g] + 128 + kf*32);
            }
            #pragma unroll
            for (int g = 0; g < 6; g++)
                #pragma unroll
                for (int mi = 0; mi < 3; mi++){
                    mma16816(acc[mi][g], Ah[mi], Bh[g]);
                    mma16816(acc[mi][g], Ah[mi], Bl[g]);
                    mma16816(acc[mi][g], Al[mi], Bh[g]);
                }
        }

        // ---- EW fully in registers: 5 element-pairs per thread ----
        #pragma unroll
        for (int rg = 0; rg < 5; rg++){
            int mi = rg >> 1, hm = rg & 1;
            float gf0 = acc[mi][0][2*hm], gf1 = acc[mi][0][2*hm+1];
            float gi0 = acc[mi][1][2*hm], gi1 = acc[mi][1][2*hm+1];
            float go0 = acc[mi][2][2*hm], go1 = acc[mi][2][2*hm+1];
            float gu0 = acc[mi][3][2*hm], gu1 = acc[mi][3][2*hm+1];
            float gG0 = acc[mi][4][2*hm], gG1 = acc[mi][4][2*hm+1];
            float gV0 = acc[mi][5][2*hm], gV1 = acc[mi][5][2*hm+1];

            float hn0, hn1;
            {
                float ef = __expf(-gf0);
                float eg = __expf(-gG0);
                float fgf = __fdividef(1.0f, 1.0f + ef + eg + ef*eg);
                float ei = __expf(-gi0);
                float eu = __expf(-gu0);
                float ev = __expf(-gV0);
                float iuu = __fdividef(1.0f, (1.0f+ei)*(1.0f+eu)*(1.0f+ev));
                float c = fgf*cst0[rg] + iuu;
                cst0[rg] = c;
                float ot = __fdividef(1.0f, 1.0f + __expf(-go0));
                float th = 1.0f - __fdividef(2.0f, 1.0f + __expf(2.0f*c));
                hn0 = ot * th;
            }
            {
                float ef = __expf(-gf1);
                float eg = __expf(-gG1);
                float fgf = __fdividef(1.0f, 1.0f + ef + eg + ef*eg);
                float ei = __expf(-gi1);
                float eu = __expf(-gu1);
                float ev = __expf(-gV1);
                float iuu = __fdividef(1.0f, (1.0f+ei)*(1.0f+eu)*(1.0f+ev));
                float c = fgf*cst1[rg] + iuu;
                cst1[rg] = c;
                float ot = __fdividef(1.0f, 1.0f + __expf(-go1));
                float th = 1.0f - __fdividef(2.0f, 1.0f + __expf(2.0f*c));
                hn1 = ot * th;
            }

            // write h (hi/lo bf16) into hout
            u32 hhi = bfpack(hn0, hn1);
            float r0 = hn0 - __uint_as_float(hhi << 16);
            float r1 = hn1 - __uint_as_float(hhi & 0xFFFF0000u);
            u32 hlo = bfpack(r0, r1);
            int hpi = 4*w + tid4;
            *(u32*)(smem + hout + rrow[rg]*HPITCH + 4*hpi)       = hhi;
            *(u32*)(smem + hout + rrow[rg]*HPITCH + 128 + 4*hpi) = hlo;

            float2 hv = make_float2(hn0, hn1);
            *(float2*)&hidden[gb[rg] + t*HSTRIDE] = hv;
            if (t == NT-1){
                *(float2*)&htp[fb[rg]] = hv;
                *(float2*)&ctp[fb[rg]] = make_float2(cst0[rg], cst1[rg]);
            }
        }
        __syncthreads();   // h(t) published before step t+1 ldsm
    }
}

extern "C" void kernel_launch(void* const* d_in, const int* in_sizes, int n_in,
                              void* d_out, int out_size)
{
    const float* x   = (const float*)d_in[0];
    const float* o_s = (const float*)d_in[1];
    const float* Ux  = (const float*)d_in[2];
    const float* Vx  = (const float*)d_in[3];
    const float* bx  = (const float*)d_in[4];
    const float* Ug  = (const float*)d_in[5];
    const float* Vg  = (const float*)d_in[6];
    const float* bg  = (const float*)d_in[7];

    float* out    = (float*)d_out;
    float* hidden = out;                               // [B,T,N,H]
    float* htp    = out + (size_t)BTN * NH;            // [B,N,H]
    float* ctp    = htp + (size_t)NROWS * NH;          // [B,N,H]

    cudaFuncSetAttribute(glstm_pre_mma, cudaFuncAttributeMaxDynamicSharedMemorySize, P1_SMEM);
    cudaFuncSetAttribute(glstm_rec_mma, cudaFuncAttributeMaxDynamicSharedMemorySize, P2_SMEM);

    glstm_pre_mma<<<P1_GRID, P1_THREADS, P1_SMEM>>>(x, o_s, Ux, bx, Ug, bg);
    glstm_rec_mma<<<P2_BLOCKS, P2_THREADS, P2_SMEM>>>(Vx, Vg, hidden, htp, ctp);
}